// round 1
// baseline (speedup 1.0000x reference)
#include <cuda_runtime.h>
#include <math.h>

#define Bsz 16
#define Nn  256
#define Ll  64
#define Hh  32
#define HEe 128
#define EOo 64
#define LALPHA 0.2f

// Scratch (device globals: allocation-free per harness rules)
__device__ float g_h  [Bsz*Nn*Hh];    // node features [B,N,32]
__device__ float g_rcv[Bsz*Nn*HEe];   // receiver proj [B,N,128]
__device__ float g_snd[Bsz*Nn*HEe];   // sender proj   [B,N,128]
__device__ float g_m  [Bsz*Nn*EOo];   // aggregated messages [B,N,64]

__device__ __forceinline__ float lrelu(float v) {
    // v>=0: v >= 0.2v ; v<0: 0.2v > v  -> fmaxf is exact branchless lrelu
    return fmaxf(v, LALPHA * v);
}

// -------------------------------------------------------------------------
// K1: h0[b,n,:] = ((x[b] @ W_lin[:, n*64:(n+1)*64]) + b_lin) @ W_in + b_in
// one block per (b,n), 64 threads
// -------------------------------------------------------------------------
__global__ void k_init(const float* __restrict__ x,
                       const float* __restrict__ W_lin,
                       const float* __restrict__ b_lin,
                       const float* __restrict__ W_in,
                       const float* __restrict__ b_in) {
    const int bi = blockIdx.x;          // b*256 + n
    const int b  = bi >> 8;
    const int n  = bi & 255;
    __shared__ float xs[Ll];
    __shared__ float ts[Ll];
    const int tid = threadIdx.x;        // 0..63

    xs[tid] = x[b*Ll + tid];
    __syncthreads();

    float acc = b_lin[n*Ll + tid];
    const float* wcol = W_lin + n*Ll + tid;   // column (n*64 + tid), row stride 16384
    #pragma unroll 16
    for (int l2 = 0; l2 < Ll; l2++)
        acc += xs[l2] * wcol[(size_t)l2 * (Nn*Ll)];
    ts[tid] = acc;
    __syncthreads();

    if (tid < Hh) {
        float a2 = b_in[tid];
        #pragma unroll
        for (int l = 0; l < Ll; l++)
            a2 += ts[l] * W_in[l*Hh + tid];
        g_h[bi*Hh + tid] = a2;
    }
}

// -------------------------------------------------------------------------
// K2: rcv = h @ We1[t][:32], snd = h @ We1[t][32:]
// block: 128 threads, 32 rows per block. grid = 4096/32 = 128
// -------------------------------------------------------------------------
__global__ void k_rs(const float* __restrict__ We1_t) {
    __shared__ float W1s[2*Hh*HEe];   // [64][128]  32KB
    __shared__ float hs[32*Hh];       // 32 rows x 32
    const int tid  = threadIdx.x;     // 0..127
    const int base = blockIdx.x * 32; // row base

    for (int i = tid; i < 2*Hh*HEe; i += 128) W1s[i] = We1_t[i];
    for (int i = tid; i < 32*Hh;    i += 128) hs[i]  = g_h[base*Hh + i];
    __syncthreads();

    const int k = tid;                // 0..127 (HE column)
    for (int r = 0; r < 32; r++) {
        float ra = 0.f, sa = 0.f;
        #pragma unroll
        for (int hh = 0; hh < Hh; hh++) {
            float hv = hs[r*Hh + hh];
            ra += hv * W1s[hh*HEe + k];
            sa += hv * W1s[(Hh + hh)*HEe + k];
        }
        g_rcv[(size_t)(base + r)*HEe + k] = ra;
        g_snd[(size_t)(base + r)*HEe + k] = sa;
    }
}

// -------------------------------------------------------------------------
// K3 (dominant): for block (b,i):
//   m[b,i,o] = sum_j lrelu( sum_k lrelu(rcv[i,k]+snd[j,k]+be1[k]) * We2[k,o] + be2[o] )
// 256 threads: A-tile [64 j x 128 k] generated in smem per chunk, then
// register-tiled GEMM (4x4 per thread over 64x64), lrelu + j-reduce.
// -------------------------------------------------------------------------
#define AS_STRIDE 132   // 128 + 4 pad (keeps 16B alignment, kills bank conflicts)

__global__ void k_edge(const float* __restrict__ We2_t,
                       const float* __restrict__ be1_t,
                       const float* __restrict__ be2_t) {
    extern __shared__ float sm[];
    float* We2s = sm;                       // 128*64 = 8192
    float* As   = sm + 8192;                // 64*132 = 8448 (also reused for reduction)
    float* rbs  = sm + 8192 + 8448;         // 128: rcv + be1
    float* be2s = rbs + 128;                // 64

    const int tid = threadIdx.x;            // 0..255
    const int bi  = blockIdx.x;             // b*256 + i
    const int b   = bi >> 8;

    for (int idx = tid; idx < HEe*EOo; idx += 256)
        We2s[idx] = We2_t[idx];
    if (tid < HEe)                  rbs[tid]        = g_rcv[(size_t)bi*HEe + tid] + be1_t[tid];
    else if (tid < HEe + EOo)       be2s[tid - HEe] = be2_t[tid - HEe];

    const int tx = tid & 15;                // o / 4
    const int ty = tid >> 4;                // j / 4 (within 64-chunk)
    const int lane = tid & 31, w = tid >> 5;

    float psum[4] = {0.f, 0.f, 0.f, 0.f};
    const float* sndb = g_snd + (size_t)(b * Nn) * HEe;

    for (int jc = 0; jc < 4; jc++) {
        __syncthreads();
        // ---- generate A chunk: 64 j x 128 k, layout [j][k] ----
        {
            const int k4 = lane * 4;
            float4 rb = *(const float4*)&rbs[k4];
            #pragma unroll
            for (int r = 0; r < 8; r++) {
                const int j = w * 8 + r;
                float4 s = *(const float4*)&sndb[(size_t)(jc*64 + j)*HEe + k4];
                float4 a;
                a.x = lrelu(s.x + rb.x);
                a.y = lrelu(s.y + rb.y);
                a.z = lrelu(s.z + rb.z);
                a.w = lrelu(s.w + rb.w);
                *(float4*)&As[j*AS_STRIDE + k4] = a;
            }
        }
        __syncthreads();

        // ---- 64x64x128 GEMM, 4x4 micro-tile per thread ----
        float acc[4][4];
        #pragma unroll
        for (int r = 0; r < 4; r++)
            #pragma unroll
            for (int c = 0; c < 4; c++) acc[r][c] = 0.f;

        const float* a0p = &As[(ty*4 + 0)*AS_STRIDE];
        const float* a1p = &As[(ty*4 + 1)*AS_STRIDE];
        const float* a2p = &As[(ty*4 + 2)*AS_STRIDE];
        const float* a3p = &As[(ty*4 + 3)*AS_STRIDE];

        #pragma unroll 8
        for (int k = 0; k < HEe; k++) {
            float4 bb = *(const float4*)&We2s[k*EOo + tx*4];
            float a0 = a0p[k], a1 = a1p[k], a2 = a2p[k], a3 = a3p[k];
            acc[0][0] += a0*bb.x; acc[0][1] += a0*bb.y; acc[0][2] += a0*bb.z; acc[0][3] += a0*bb.w;
            acc[1][0] += a1*bb.x; acc[1][1] += a1*bb.y; acc[1][2] += a1*bb.z; acc[1][3] += a1*bb.w;
            acc[2][0] += a2*bb.x; acc[2][1] += a2*bb.y; acc[2][2] += a2*bb.z; acc[2][3] += a2*bb.w;
            acc[3][0] += a3*bb.x; acc[3][1] += a3*bb.y; acc[3][2] += a3*bb.z; acc[3][3] += a3*bb.w;
        }

        // ---- per-(j,o) lrelu then partial j-reduce ----
        #pragma unroll
        for (int c = 0; c < 4; c++) {
            float bo = be2s[tx*4 + c];
            #pragma unroll
            for (int r = 0; r < 4; r++)
                psum[c] += lrelu(acc[r][c] + bo);
        }
    }

    // ---- reduce psum across the 16 ty groups (reuse As; stride 68 = 272B, 16B aligned) ----
    __syncthreads();
    *(float4*)&As[ty*68 + tx*4] = make_float4(psum[0], psum[1], psum[2], psum[3]);
    __syncthreads();
    if (tid < EOo) {
        float s = 0.f;
        #pragma unroll
        for (int g = 0; g < 16; g++) s += As[g*68 + tid];
        g_m[(size_t)bi*EOo + tid] = s;
    }
}

// -------------------------------------------------------------------------
// K4: node update.  n0 = lrelu([h,m] @ Wn0 + bn0);  h' = lrelu(n0 @ Wn1 + bn1)
// last round: out = tanh(h'). One block (32 threads) per row.
// -------------------------------------------------------------------------
__global__ void k_node(const float* __restrict__ Wn0_t,
                       const float* __restrict__ bn0_t,
                       const float* __restrict__ Wn1_t,
                       const float* __restrict__ bn1_t,
                       float* __restrict__ out, int last) {
    const int row = blockIdx.x;         // 0..4095
    const int o   = threadIdx.x;        // 0..31
    __shared__ float fs[Hh + EOo];      // 96
    __shared__ float n0s[Hh];

    fs[o]        = g_h[(size_t)row*Hh + o];
    fs[Hh + o]        = g_m[(size_t)row*EOo + o];
    fs[Hh + Hh + o]   = g_m[(size_t)row*EOo + Hh + o];
    __syncthreads();

    float a = bn0_t[o];
    #pragma unroll
    for (int f = 0; f < Hh + EOo; f++)
        a += fs[f] * Wn0_t[f*Hh + o];
    n0s[o] = lrelu(a);
    __syncthreads();

    float a2 = bn1_t[o];
    #pragma unroll
    for (int f = 0; f < Hh; f++)
        a2 += n0s[f] * Wn1_t[f*Hh + o];
    a2 = lrelu(a2);

    if (last) out[(size_t)row*Hh + o] = tanhf(a2);
    else      g_h[(size_t)row*Hh + o] = a2;
}

// -------------------------------------------------------------------------
extern "C" void kernel_launch(void* const* d_in, const int* in_sizes, int n_in,
                              void* d_out, int out_size) {
    const float* x     = (const float*)d_in[0];
    const float* W_lin = (const float*)d_in[1];
    const float* b_lin = (const float*)d_in[2];
    const float* W_in  = (const float*)d_in[3];
    const float* b_in  = (const float*)d_in[4];
    const float* We1   = (const float*)d_in[5];   // [3, 64, 128]
    const float* be1   = (const float*)d_in[6];   // [3, 128]
    const float* We2   = (const float*)d_in[7];   // [3, 128, 64]
    const float* be2   = (const float*)d_in[8];   // [3, 64]
    const float* Wn0   = (const float*)d_in[9];   // [3, 96, 32]
    const float* bn0   = (const float*)d_in[10];  // [3, 32]
    const float* Wn1   = (const float*)d_in[11];  // [3, 32, 32]
    const float* bn1   = (const float*)d_in[12];  // [3, 32]
    float* out = (float*)d_out;

    const int edge_smem = (8192 + 8448 + 128 + 64) * (int)sizeof(float); // 67328B
    cudaFuncSetAttribute(k_edge, cudaFuncAttributeMaxDynamicSharedMemorySize, edge_smem);

    k_init<<<Bsz*Nn, 64>>>(x, W_lin, b_lin, W_in, b_in);
    for (int t = 0; t < 3; t++) {
        k_rs  <<<(Bsz*Nn)/32, 128>>>(We1 + (size_t)t * 2*Hh*HEe);
        k_edge<<<Bsz*Nn, 256, edge_smem>>>(We2 + (size_t)t * HEe*EOo,
                                           be1 + t*HEe, be2 + t*EOo);
        k_node<<<Bsz*Nn, 32>>>(Wn0 + (size_t)t * (Hh+EOo)*Hh, bn0 + t*Hh,
                               Wn1 + (size_t)t * Hh*Hh,        bn1 + t*Hh,
                               out, t == 2);
    }
}

// round 3
// speedup vs baseline: 2.8555x; 2.8555x over previous
#include <cuda_runtime.h>
#include <cuda_fp16.h>
#include <cstdint>
#include <math.h>

#define Bsz 16
#define Nn  256
#define Ll  64
#define Hh  32
#define HEe 128
#define EOo 64
#define LALPHA 0.2f
#define BT_STRIDE 136   // fp16 elems per row of BT (128 + 8 pad -> conflict-free)

// ---------------- device scratch (no allocs allowed) ----------------
__device__ float g_h  [Bsz*Nn*Hh];
__device__ float g_rcv[Bsz*Nn*HEe];
__device__ float g_snd[Bsz*Nn*HEe];
__device__ float g_m  [Bsz*Nn*EOo];
__device__ __align__(16) __half g_Bt[EOo * BT_STRIDE];   // We2^T fp16, padded

__device__ __forceinline__ float lrelu(float v) { return fmaxf(v, LALPHA * v); }

// ---------------- K1: h0 init ----------------
__global__ void k_init(const float* __restrict__ x, const float* __restrict__ W_lin,
                       const float* __restrict__ b_lin, const float* __restrict__ W_in,
                       const float* __restrict__ b_in) {
    const int bi = blockIdx.x, b = bi >> 8, n = bi & 255;
    __shared__ float xs[Ll], ts[Ll];
    const int tid = threadIdx.x;
    xs[tid] = x[b*Ll + tid];
    __syncthreads();
    float acc = b_lin[n*Ll + tid];
    const float* wcol = W_lin + n*Ll + tid;
    #pragma unroll 16
    for (int l2 = 0; l2 < Ll; l2++) acc += xs[l2] * wcol[(size_t)l2 * (Nn*Ll)];
    ts[tid] = acc;
    __syncthreads();
    if (tid < Hh) {
        float a2 = b_in[tid];
        #pragma unroll
        for (int l = 0; l < Ll; l++) a2 += ts[l] * W_in[l*Hh + tid];
        g_h[bi*Hh + tid] = a2;
    }
}

// ---------------- K2: rcv/snd projections ----------------
__global__ void k_rs(const float* __restrict__ We1_t) {
    __shared__ float W1s[2*Hh*HEe];
    __shared__ float hs[32*Hh];
    const int tid = threadIdx.x, base = blockIdx.x * 32;
    for (int i = tid; i < 2*Hh*HEe; i += 128) W1s[i] = We1_t[i];
    for (int i = tid; i < 32*Hh;    i += 128) hs[i]  = g_h[base*Hh + i];
    __syncthreads();
    const int k = tid;
    for (int r = 0; r < 32; r++) {
        float ra = 0.f, sa = 0.f;
        #pragma unroll
        for (int hh = 0; hh < Hh; hh++) {
            float hv = hs[r*Hh + hh];
            ra += hv * W1s[hh*HEe + k];
            sa += hv * W1s[(Hh + hh)*HEe + k];
        }
        g_rcv[(size_t)(base + r)*HEe + k] = ra;
        g_snd[(size_t)(base + r)*HEe + k] = sa;
    }
}

// ---------------- K-prep: We2 [128][64] f32 -> BT fp16 [64][BT_STRIDE] ----------------
__global__ void k_prep(const float* __restrict__ We2_t) {
    const int tid = threadIdx.x;
    for (int p = tid; p < EOo * HEe; p += 128) {
        int o = p & 63, k = p >> 6;
        g_Bt[o * BT_STRIDE + k] = __float2half(We2_t[k * EOo + o]);
    }
}

// ---------------- K3: HMMA edge kernel ----------------
// C[j,o] = A[j,k] @ We2[k,o];  A[j,k] = lrelu(rcv[i,k] + snd[j,k] + be1[k])
// 8 warps; warp w owns j rows [32w, 32w+32). m16n8k16, 2 m-tiles x 8 n-tiles x 8 k-steps.
__global__ void __launch_bounds__(256, 2) k_edge_mma(const float* __restrict__ be1_t,
                                                     const float* __restrict__ be2_t) {
    __shared__ __half BTs[EOo * BT_STRIDE];   // 17408 B
    __shared__ float  rbs[HEe];               // rcv + be1
    __shared__ float  be2s[EOo];
    __shared__ float  red[8][EOo];

    const int tid = threadIdx.x, w = tid >> 5, lane = tid & 31;
    const int bi = blockIdx.x, b = bi >> 8;
    const int q = lane & 3, rr = lane >> 2;

    // load BT (fp16 weights) into smem
    {
        const uint4* src = (const uint4*)g_Bt;
        uint4*       dst = (uint4*)BTs;
        #pragma unroll
        for (int i = 0; i < 4; i++) dst[tid + 256*i] = src[tid + 256*i];
        if (tid < 64) dst[tid + 1024] = src[tid + 1024];   // 1088 uint4 total
    }
    if (tid < HEe)            rbs[tid]        = g_rcv[(size_t)bi*HEe + tid] + be1_t[tid];
    else if (tid < HEe + EOo) be2s[tid - HEe] = be2_t[tid - HEe];
    __syncthreads();

    const float2* snd2 = (const float2*)(g_snd + (size_t)(b * Nn) * HEe);   // [j][64] float2
    const float2* rbs2 = (const float2*)rbs;

    float acc[2][8][4];
    #pragma unroll
    for (int mt = 0; mt < 2; mt++)
        #pragma unroll
        for (int nt = 0; nt < 8; nt++)
            #pragma unroll
            for (int e = 0; e < 4; e++) acc[mt][nt][e] = 0.f;

    const int jb = w * 32;

    #pragma unroll
    for (int ks = 0; ks < 8; ks++) {
        const int kb2 = ks * 8;            // float2 index of k-step base
        const int kb  = ks * 16;           // half index
        float2 rbl = rbs2[kb2 + q];        // cols c, c+1
        float2 rbh = rbs2[kb2 + 4 + q];    // cols c+8, c+9

        uint32_t afr[2][4];
        #pragma unroll
        for (int mt = 0; mt < 2; mt++) {
            const int r0 = jb + mt*16 + rr;
            float2 sA = snd2[(size_t)r0*64 + kb2 + q];
            float2 sB = snd2[(size_t)(r0+8)*64 + kb2 + q];
            float2 sC = snd2[(size_t)r0*64 + kb2 + 4 + q];
            float2 sD = snd2[(size_t)(r0+8)*64 + kb2 + 4 + q];
            __half2 h0 = __floats2half2_rn(lrelu(sA.x + rbl.x), lrelu(sA.y + rbl.y));
            __half2 h1 = __floats2half2_rn(lrelu(sB.x + rbl.x), lrelu(sB.y + rbl.y));
            __half2 h2 = __floats2half2_rn(lrelu(sC.x + rbh.x), lrelu(sC.y + rbh.y));
            __half2 h3 = __floats2half2_rn(lrelu(sD.x + rbh.x), lrelu(sD.y + rbh.y));
            afr[mt][0] = *(uint32_t*)&h0;
            afr[mt][1] = *(uint32_t*)&h1;
            afr[mt][2] = *(uint32_t*)&h2;
            afr[mt][3] = *(uint32_t*)&h3;
        }

        #pragma unroll
        for (int nt = 0; nt < 8; nt++) {
            const __half* bp = &BTs[(nt*8 + rr) * BT_STRIDE + kb + (q << 1)];
            uint32_t b0 = *(const uint32_t*)bp;
            uint32_t b1 = *(const uint32_t*)(bp + 8);
            #pragma unroll
            for (int mt = 0; mt < 2; mt++) {
                asm volatile("mma.sync.aligned.m16n8k16.row.col.f32.f16.f16.f32 "
                             "{%0,%1,%2,%3}, {%4,%5,%6,%7}, {%8,%9}, {%0,%1,%2,%3};"
                             : "+f"(acc[mt][nt][0]), "+f"(acc[mt][nt][1]),
                               "+f"(acc[mt][nt][2]), "+f"(acc[mt][nt][3])
                             : "r"(afr[mt][0]), "r"(afr[mt][1]), "r"(afr[mt][2]), "r"(afr[mt][3]),
                               "r"(b0), "r"(b1));
            }
        }
    }

    // epilogue: lrelu(acc + be2), sum over j (rows), reduce
    #pragma unroll
    for (int nt = 0; nt < 8; nt++) {
        const int o0 = nt*8 + (q << 1);
        const float bo0 = be2s[o0], bo1 = be2s[o0 + 1];
        float s0 = lrelu(acc[0][nt][0] + bo0) + lrelu(acc[0][nt][2] + bo0)
                 + lrelu(acc[1][nt][0] + bo0) + lrelu(acc[1][nt][2] + bo0);
        float s1 = lrelu(acc[0][nt][1] + bo1) + lrelu(acc[0][nt][3] + bo1)
                 + lrelu(acc[1][nt][1] + bo1) + lrelu(acc[1][nt][3] + bo1);
        #pragma unroll
        for (int d = 4; d < 32; d <<= 1) {
            s0 += __shfl_xor_sync(0xFFFFFFFFu, s0, d);
            s1 += __shfl_xor_sync(0xFFFFFFFFu, s1, d);
        }
        if (lane < 4) { red[w][o0] = s0; red[w][o0 + 1] = s1; }
    }
    __syncthreads();

    if (tid < EOo) {
        float s = 0.f;
        #pragma unroll
        for (int g = 0; g < 8; g++) s += red[g][tid];
        g_m[(size_t)bi*EOo + tid] = s;
    }
}

// ---------------- K4: node update ----------------
__global__ void k_node(const float* __restrict__ Wn0_t, const float* __restrict__ bn0_t,
                       const float* __restrict__ Wn1_t, const float* __restrict__ bn1_t,
                       float* __restrict__ out, int last) {
    const int row = blockIdx.x, o = threadIdx.x;
    __shared__ float fs[Hh + EOo];
    __shared__ float n0s[Hh];
    fs[o]           = g_h[(size_t)row*Hh + o];
    fs[Hh + o]      = g_m[(size_t)row*EOo + o];
    fs[Hh + Hh + o] = g_m[(size_t)row*EOo + Hh + o];
    __syncthreads();
    float a = bn0_t[o];
    #pragma unroll
    for (int f = 0; f < Hh + EOo; f++) a += fs[f] * Wn0_t[f*Hh + o];
    n0s[o] = lrelu(a);
    __syncthreads();
    float a2 = bn1_t[o];
    #pragma unroll
    for (int f = 0; f < Hh; f++) a2 += n0s[f] * Wn1_t[f*Hh + o];
    a2 = lrelu(a2);
    if (last) out[(size_t)row*Hh + o] = tanhf(a2);
    else      g_h[(size_t)row*Hh + o] = a2;
}

// ---------------- launch ----------------
extern "C" void kernel_launch(void* const* d_in, const int* in_sizes, int n_in,
                              void* d_out, int out_size) {
    const float* x     = (const float*)d_in[0];
    const float* W_lin = (const float*)d_in[1];
    const float* b_lin = (const float*)d_in[2];
    const float* W_in  = (const float*)d_in[3];
    const float* b_in  = (const float*)d_in[4];
    const float* We1   = (const float*)d_in[5];
    const float* be1   = (const float*)d_in[6];
    const float* We2   = (const float*)d_in[7];
    const float* be2   = (const float*)d_in[8];
    const float* Wn0   = (const float*)d_in[9];
    const float* bn0   = (const float*)d_in[10];
    const float* Wn1   = (const float*)d_in[11];
    const float* bn1   = (const float*)d_in[12];
    float* out = (float*)d_out;

    k_init<<<Bsz*Nn, 64>>>(x, W_lin, b_lin, W_in, b_in);
    for (int t = 0; t < 3; t++) {
        k_prep<<<1, 128>>>(We2 + (size_t)t * HEe*EOo);
        k_rs  <<<(Bsz*Nn)/32, 128>>>(We1 + (size_t)t * 2*Hh*HEe);
        k_edge_mma<<<Bsz*Nn, 256>>>(be1 + t*HEe, be2 + t*EOo);
        k_node<<<Bsz*Nn, 32>>>(Wn0 + (size_t)t * (Hh+EOo)*Hh, bn0 + t*Hh,
                               Wn1 + (size_t)t * Hh*Hh,        bn1 + t*Hh,
                               out, t == 2);
    }
}

// round 4
// speedup vs baseline: 4.3011x; 1.5062x over previous
#include <cuda_runtime.h>
#include <cuda_fp16.h>
#include <cstdint>
#include <math.h>

#define Bsz 16
#define Nn  256
#define Ll  64
#define Hh  32
#define HEe 128
#define EOo 64
#define LALPHA 0.2f

// ---------------- device scratch (no allocs allowed) ----------------
__device__ float g_h  [Bsz*Nn*Hh];
__device__ float g_rcv[Bsz*Nn*HEe];
__device__ float g_snd[Bsz*Nn*HEe];
__device__ float g_mp [4][Bsz*Nn][EOo];          // per-j-tile partial message sums (4MB)
__device__ __align__(16) uint4 g_Bfrag[32*32];   // We2 fp16 in mma-fragment layout

__device__ __forceinline__ float lrelu(float v) { return fmaxf(v, LALPHA * v); }

// ---------------- K1: h0 init ----------------
__global__ void k_init(const float* __restrict__ x, const float* __restrict__ W_lin,
                       const float* __restrict__ b_lin, const float* __restrict__ W_in,
                       const float* __restrict__ b_in) {
    const int bi = blockIdx.x, b = bi >> 8, n = bi & 255;
    __shared__ float xs[Ll], ts[Ll];
    const int tid = threadIdx.x;
    xs[tid] = x[b*Ll + tid];
    __syncthreads();
    float acc = b_lin[n*Ll + tid];
    const float* wcol = W_lin + n*Ll + tid;
    #pragma unroll 16
    for (int l2 = 0; l2 < Ll; l2++) acc += xs[l2] * wcol[(size_t)l2 * (Nn*Ll)];
    ts[tid] = acc;
    __syncthreads();
    if (tid < Hh) {
        float a2 = b_in[tid];
        #pragma unroll
        for (int l = 0; l < Ll; l++) a2 += ts[l] * W_in[l*Hh + tid];
        g_h[bi*Hh + tid] = a2;
    }
}

// ---------------- K2: rcv/snd projections ----------------
__global__ void k_rs(const float* __restrict__ We1_t) {
    __shared__ float W1s[2*Hh*HEe];
    __shared__ float hs[32*Hh];
    const int tid = threadIdx.x, base = blockIdx.x * 32;
    for (int i = tid; i < 2*Hh*HEe; i += 128) W1s[i] = We1_t[i];
    for (int i = tid; i < 32*Hh;    i += 128) hs[i]  = g_h[base*Hh + i];
    __syncthreads();
    const int k = tid;
    for (int r = 0; r < 32; r++) {
        float ra = 0.f, sa = 0.f;
        #pragma unroll
        for (int hh = 0; hh < Hh; hh++) {
            float hv = hs[r*Hh + hh];
            ra += hv * W1s[hh*HEe + k];
            sa += hv * W1s[(Hh + hh)*HEe + k];
        }
        g_rcv[(size_t)(base + r)*HEe + k] = ra;
        g_snd[(size_t)(base + r)*HEe + k] = sa;
    }
}

// ---------------- K-prep: We2 [128][64] f32 -> fragment-layout fp16 ----------------
// g_Bfrag[chunk][lane], chunk = ks*4 + ntp (ntp = nt/2), lane = rr*4 + q.
// uint4 = { b0(nt=2ntp), b1(2ntp), b0(2ntp+1), b1(2ntp+1) }
// b0(nt) = half2( We2[k][o], We2[k+1][o] ), b1(nt) = half2( We2[k+8][o], We2[k+9][o] )
// with k = ks*16 + 2q, o = nt*8 + rr.
__global__ void k_prep(const float* __restrict__ We2_t) {
    const int tid = threadIdx.x;   // 256 threads
    for (int e = tid; e < 1024; e += 256) {
        const int chunk = e >> 5, lane = e & 31;
        const int ks = chunk >> 2, ntp = chunk & 3;
        const int rr = lane >> 2,  q = lane & 3;
        const int k = ks*16 + 2*q;
        uint32_t bv[4];
        #pragma unroll
        for (int s = 0; s < 2; s++) {
            const int o = (2*ntp + s)*8 + rr;
            __half2 h0 = __floats2half2_rn(We2_t[k*EOo + o],     We2_t[(k+1)*EOo + o]);
            __half2 h1 = __floats2half2_rn(We2_t[(k+8)*EOo + o], We2_t[(k+9)*EOo + o]);
            bv[2*s]   = *(uint32_t*)&h0;
            bv[2*s+1] = *(uint32_t*)&h1;
        }
        g_Bfrag[e] = make_uint4(bv[0], bv[1], bv[2], bv[3]);
    }
}

// ---------------- K3: tiled HMMA edge kernel ----------------
// CTA = (b, it, jt): 32 i x 64 j. rows of GEMM = (i,j) pairs, k=128, n=64.
// smem: snd[64][136] f32, rcv+be1[32][132] f32, be2[64].
#define SND_STR 136
#define RCV_STR 132
#define EDGE_SMEM ((64*SND_STR + 32*RCV_STR + 64) * 4)

__global__ void __launch_bounds__(256, 1) k_edge3(const float* __restrict__ be1_t,
                                                  const float* __restrict__ be2_t) {
    extern __shared__ float sm[];
    float* snd_s = sm;                       // [64][136]
    float* rcv_s = sm + 64*SND_STR;          // [32][132]
    float* be2s  = sm + 64*SND_STR + 32*RCV_STR;

    const int tid = threadIdx.x, w = tid >> 5, lane = tid & 31;
    const int q = lane & 3, rr = lane >> 2;
    const int jt = blockIdx.x & 3, it = (blockIdx.x >> 2) & 7, b = blockIdx.x >> 5;

    // ---- register-resident B fragments (loaded once, coalesced) ----
    uint4 breg[32];
    #pragma unroll
    for (int c = 0; c < 32; c++) breg[c] = g_Bfrag[c*32 + lane];

    // ---- stage snd j-tile ----
    {
        const float4* sndg = (const float4*)(g_snd + (size_t)(b*Nn + jt*64)*HEe);
        for (int p = tid; p < 64*32; p += 256) {
            const int r = p >> 5, c4 = p & 31;
            *(float4*)&snd_s[r*SND_STR + c4*4] = sndg[r*32 + c4];
        }
    }
    // ---- stage rcv i-tile (+be1) ----
    {
        const float4* rcvg = (const float4*)(g_rcv + (size_t)(b*Nn + it*32)*HEe);
        const float4* be1g = (const float4*)be1_t;
        for (int p = tid; p < 32*32; p += 256) {
            const int r = p >> 5, c4 = p & 31;
            float4 v = rcvg[r*32 + c4];
            float4 bb = be1g[c4];
            v.x += bb.x; v.y += bb.y; v.z += bb.z; v.w += bb.w;
            *(float4*)&rcv_s[r*RCV_STR + c4*4] = v;
        }
    }
    if (tid < EOo) be2s[tid] = be2_t[tid];
    __syncthreads();

    const __half2 alpha2 = __floats2half2_rn(LALPHA, LALPHA);

    // warp w handles i_loc in {4w..4w+3}; all 64 j (4 m-tiles of 16)
    for (int ii = 0; ii < 4; ii++) {
        const int iloc = w*4 + ii;
        const float* rcvp = &rcv_s[iloc*RCV_STR];

        float s[8][2];
        #pragma unroll
        for (int nt = 0; nt < 8; nt++) { s[nt][0] = 0.f; s[nt][1] = 0.f; }

        for (int mj = 0; mj < 4; mj++) {
            const float* sp = &snd_s[(mj*16 + rr)*SND_STR];
            float acc[8][4];
            #pragma unroll
            for (int nt = 0; nt < 8; nt++)
                { acc[nt][0]=0.f; acc[nt][1]=0.f; acc[nt][2]=0.f; acc[nt][3]=0.f; }

            #pragma unroll
            for (int ks = 0; ks < 8; ks++) {
                const int kb = ks*16 + 2*q;
                float2 rc0 = *(const float2*)&rcvp[kb];
                float2 rc1 = *(const float2*)&rcvp[kb + 8];
                float2 s00 = *(const float2*)&sp[kb];
                float2 s10 = *(const float2*)&sp[8*SND_STR + kb];
                float2 s01 = *(const float2*)&sp[kb + 8];
                float2 s11 = *(const float2*)&sp[8*SND_STR + kb + 8];

                __half2 a0 = __floats2half2_rn(s00.x + rc0.x, s00.y + rc0.y);
                __half2 a1 = __floats2half2_rn(s10.x + rc0.x, s10.y + rc0.y);
                __half2 a2 = __floats2half2_rn(s01.x + rc1.x, s01.y + rc1.y);
                __half2 a3 = __floats2half2_rn(s11.x + rc1.x, s11.y + rc1.y);
                a0 = __hmax2(a0, __hmul2(a0, alpha2));
                a1 = __hmax2(a1, __hmul2(a1, alpha2));
                a2 = __hmax2(a2, __hmul2(a2, alpha2));
                a3 = __hmax2(a3, __hmul2(a3, alpha2));
                const uint32_t A0 = *(uint32_t*)&a0, A1 = *(uint32_t*)&a1;
                const uint32_t A2 = *(uint32_t*)&a2, A3 = *(uint32_t*)&a3;

                #pragma unroll
                for (int nt = 0; nt < 8; nt++) {
                    const uint4 bb = breg[ks*4 + (nt >> 1)];
                    const uint32_t b0 = (nt & 1) ? bb.z : bb.x;
                    const uint32_t b1 = (nt & 1) ? bb.w : bb.y;
                    asm volatile("mma.sync.aligned.m16n8k16.row.col.f32.f16.f16.f32 "
                                 "{%0,%1,%2,%3}, {%4,%5,%6,%7}, {%8,%9}, {%0,%1,%2,%3};"
                                 : "+f"(acc[nt][0]), "+f"(acc[nt][1]),
                                   "+f"(acc[nt][2]), "+f"(acc[nt][3])
                                 : "r"(A0), "r"(A1), "r"(A2), "r"(A3), "r"(b0), "r"(b1));
                }
            }

            // drain: lrelu(acc + be2), sum over the 16 j-rows of this m-tile
            #pragma unroll
            for (int nt = 0; nt < 8; nt++) {
                const float o0 = be2s[nt*8 + 2*q], o1 = be2s[nt*8 + 2*q + 1];
                s[nt][0] += lrelu(acc[nt][0] + o0) + lrelu(acc[nt][2] + o0);
                s[nt][1] += lrelu(acc[nt][1] + o1) + lrelu(acc[nt][3] + o1);
            }
        }

        // reduce j-sums across rr groups (lanes sharing q)
        #pragma unroll
        for (int nt = 0; nt < 8; nt++) {
            #pragma unroll
            for (int e = 0; e < 2; e++) {
                float v = s[nt][e];
                v += __shfl_xor_sync(0xFFFFFFFFu, v, 4);
                v += __shfl_xor_sync(0xFFFFFFFFu, v, 8);
                v += __shfl_xor_sync(0xFFFFFFFFu, v, 16);
                s[nt][e] = v;
            }
        }
        if (lane < 4) {    // lane == q, rr == 0
            const int row = b*Nn + it*32 + iloc;
            float* dst = &g_mp[jt][row][0];
            #pragma unroll
            for (int nt = 0; nt < 8; nt++)
                *(float2*)&dst[nt*8 + 2*q] = make_float2(s[nt][0], s[nt][1]);
        }
    }
}

// ---------------- K4: node update (sums the 4 j-tile partials) ----------------
__global__ void k_node(const float* __restrict__ Wn0_t, const float* __restrict__ bn0_t,
                       const float* __restrict__ Wn1_t, const float* __restrict__ bn1_t,
                       float* __restrict__ out, int last) {
    const int row = blockIdx.x, o = threadIdx.x;
    __shared__ float fs[Hh + EOo];
    __shared__ float n0s[Hh];
    fs[o] = g_h[(size_t)row*Hh + o];
    {
        float m0 = 0.f, m1 = 0.f;
        #pragma unroll
        for (int jtt = 0; jtt < 4; jtt++) {
            m0 += g_mp[jtt][row][o];
            m1 += g_mp[jtt][row][Hh + o];
        }
        fs[Hh + o]      = m0;
        fs[Hh + Hh + o] = m1;
    }
    __syncthreads();
    float a = bn0_t[o];
    #pragma unroll
    for (int f = 0; f < Hh + EOo; f++) a += fs[f] * Wn0_t[f*Hh + o];
    n0s[o] = lrelu(a);
    __syncthreads();
    float a2 = bn1_t[o];
    #pragma unroll
    for (int f = 0; f < Hh; f++) a2 += n0s[f] * Wn1_t[f*Hh + o];
    a2 = lrelu(a2);
    if (last) out[(size_t)row*Hh + o] = tanhf(a2);
    else      g_h[(size_t)row*Hh + o] = a2;
}

// ---------------- launch ----------------
extern "C" void kernel_launch(void* const* d_in, const int* in_sizes, int n_in,
                              void* d_out, int out_size) {
    const float* x     = (const float*)d_in[0];
    const float* W_lin = (const float*)d_in[1];
    const float* b_lin = (const float*)d_in[2];
    const float* W_in  = (const float*)d_in[3];
    const float* b_in  = (const float*)d_in[4];
    const float* We1   = (const float*)d_in[5];
    const float* be1   = (const float*)d_in[6];
    const float* We2   = (const float*)d_in[7];
    const float* be2   = (const float*)d_in[8];
    const float* Wn0   = (const float*)d_in[9];
    const float* bn0   = (const float*)d_in[10];
    const float* Wn1   = (const float*)d_in[11];
    const float* bn1   = (const float*)d_in[12];
    float* out = (float*)d_out;

    cudaFuncSetAttribute(k_edge3, cudaFuncAttributeMaxDynamicSharedMemorySize, EDGE_SMEM);

    k_init<<<Bsz*Nn, 64>>>(x, W_lin, b_lin, W_in, b_in);
    for (int t = 0; t < 3; t++) {
        k_prep<<<1, 256>>>(We2 + (size_t)t * HEe*EOo);
        k_rs  <<<(Bsz*Nn)/32, 128>>>(We1 + (size_t)t * 2*Hh*HEe);
        k_edge3<<<Bsz*8*4, 256, EDGE_SMEM>>>(be1 + t*HEe, be2 + t*EOo);
        k_node<<<Bsz*Nn, 32>>>(Wn0 + (size_t)t * (Hh+EOo)*Hh, bn0 + t*Hh,
                               Wn1 + (size_t)t * Hh*Hh,        bn1 + t*Hh,
                               out, t == 2);
    }
}

// round 5
// speedup vs baseline: 4.5619x; 1.0606x over previous
#include <cuda_runtime.h>
#include <cuda_fp16.h>
#include <cstdint>
#include <math.h>

#define Bsz 16
#define Nn  256
#define Ll  64
#define Hh  32
#define HEe 128
#define EOo 64
#define LALPHA 0.2f

// ---------------- device scratch (no allocs allowed) ----------------
__device__ float g_h  [Bsz*Nn*Hh];
__device__ float g_rcv[Bsz*Nn*HEe];
__device__ float g_snd[Bsz*Nn*HEe];
__device__ float g_mp [4][Bsz*Nn][EOo];          // per-j-tile partial message sums
__device__ __align__(16) uint4 g_Bfrag[32*32];   // We2 fp16 in mma-fragment layout

__device__ __forceinline__ float lrelu(float v) { return fmaxf(v, LALPHA * v); }

// ---------------- K1: h0 init ----------------
__global__ void k_init(const float* __restrict__ x, const float* __restrict__ W_lin,
                       const float* __restrict__ b_lin, const float* __restrict__ W_in,
                       const float* __restrict__ b_in) {
    const int bi = blockIdx.x, b = bi >> 8, n = bi & 255;
    __shared__ float xs[Ll], ts[Ll];
    const int tid = threadIdx.x;
    xs[tid] = x[b*Ll + tid];
    __syncthreads();
    float acc = b_lin[n*Ll + tid];
    const float* wcol = W_lin + n*Ll + tid;
    #pragma unroll 16
    for (int l2 = 0; l2 < Ll; l2++) acc += xs[l2] * wcol[(size_t)l2 * (Nn*Ll)];
    ts[tid] = acc;
    __syncthreads();
    if (tid < Hh) {
        float a2 = b_in[tid];
        #pragma unroll
        for (int l = 0; l < Ll; l++) a2 += ts[l] * W_in[l*Hh + tid];
        g_h[bi*Hh + tid] = a2;
    }
}

// ---------------- K2: rcv/snd projections ----------------
__global__ void k_rs(const float* __restrict__ We1_t) {
    __shared__ float W1s[2*Hh*HEe];
    __shared__ float hs[32*Hh];
    const int tid = threadIdx.x, base = blockIdx.x * 32;
    for (int i = tid; i < 2*Hh*HEe; i += 128) W1s[i] = We1_t[i];
    for (int i = tid; i < 32*Hh;    i += 128) hs[i]  = g_h[base*Hh + i];
    __syncthreads();
    const int k = tid;
    for (int r = 0; r < 32; r++) {
        float ra = 0.f, sa = 0.f;
        #pragma unroll
        for (int hh = 0; hh < Hh; hh++) {
            float hv = hs[r*Hh + hh];
            ra += hv * W1s[hh*HEe + k];
            sa += hv * W1s[(Hh + hh)*HEe + k];
        }
        g_rcv[(size_t)(base + r)*HEe + k] = ra;
        g_snd[(size_t)(base + r)*HEe + k] = sa;
    }
}

// ---------------- K-prep: We2 [128][64] f32 -> fragment-layout fp16 ----------------
// g_Bfrag[chunk][lane], chunk = ks*4 + ntp (ntp = nt/2), lane = rr*4 + q.
__global__ void k_prep(const float* __restrict__ We2_t) {
    const int tid = threadIdx.x;   // 256 threads
    for (int e = tid; e < 1024; e += 256) {
        const int chunk = e >> 5, lane = e & 31;
        const int ks = chunk >> 2, ntp = chunk & 3;
        const int rr = lane >> 2,  q = lane & 3;
        const int k = ks*16 + 2*q;
        uint32_t bv[4];
        #pragma unroll
        for (int s = 0; s < 2; s++) {
            const int o = (2*ntp + s)*8 + rr;
            __half2 h0 = __floats2half2_rn(We2_t[k*EOo + o],     We2_t[(k+1)*EOo + o]);
            __half2 h1 = __floats2half2_rn(We2_t[(k+8)*EOo + o], We2_t[(k+9)*EOo + o]);
            bv[2*s]   = *(uint32_t*)&h0;
            bv[2*s+1] = *(uint32_t*)&h1;
        }
        g_Bfrag[e] = make_uint4(bv[0], bv[1], bv[2], bv[3]);
    }
}

// ---------------- K3: tiled HMMA edge kernel, n-split for occupancy ----------------
// CTA = (b, it, jt, oh): 32 i x 64 j x 32 o (o-half). grid 1024, 2 CTAs/SM.
#define SND_STR 136
#define RCV_STR 132
#define EDGE_SMEM ((64*SND_STR + 32*RCV_STR + 64) * 4)

__global__ void __launch_bounds__(256, 2) k_edge4(const float* __restrict__ be1_t,
                                                  const float* __restrict__ be2_t) {
    extern __shared__ float sm[];
    float* snd_s = sm;                       // [64][136]
    float* rcv_s = sm + 64*SND_STR;          // [32][132]
    float* be2s  = sm + 64*SND_STR + 32*RCV_STR;   // this CTA's 32 o's

    const int tid = threadIdx.x, w = tid >> 5, lane = tid & 31;
    const int q = lane & 3, rr = lane >> 2;
    const int bix = blockIdx.x;
    const int oh = bix & 1, jt = (bix >> 1) & 3, it = (bix >> 3) & 7, b = bix >> 6;

    // ---- register-resident B fragments: this CTA's o-half (16 uint4 = 64 regs) ----
    uint4 breg[16];
    #pragma unroll
    for (int ks = 0; ks < 8; ks++) {
        breg[ks*2 + 0] = g_Bfrag[(ks*4 + 2*oh + 0)*32 + lane];
        breg[ks*2 + 1] = g_Bfrag[(ks*4 + 2*oh + 1)*32 + lane];
    }

    // ---- stage snd j-tile ----
    {
        const float4* sndg = (const float4*)(g_snd + (size_t)(b*Nn + jt*64)*HEe);
        for (int p = tid; p < 64*32; p += 256) {
            const int r = p >> 5, c4 = p & 31;
            *(float4*)&snd_s[r*SND_STR + c4*4] = sndg[r*32 + c4];
        }
    }
    // ---- stage rcv i-tile (+be1) ----
    {
        const float4* rcvg = (const float4*)(g_rcv + (size_t)(b*Nn + it*32)*HEe);
        const float4* be1g = (const float4*)be1_t;
        for (int p = tid; p < 32*32; p += 256) {
            const int r = p >> 5, c4 = p & 31;
            float4 v = rcvg[r*32 + c4];
            float4 bb = be1g[c4];
            v.x += bb.x; v.y += bb.y; v.z += bb.z; v.w += bb.w;
            *(float4*)&rcv_s[r*RCV_STR + c4*4] = v;
        }
    }
    if (tid < 32) be2s[tid] = be2_t[oh*32 + tid];
    __syncthreads();

    const __half2 alpha2 = __floats2half2_rn(LALPHA, LALPHA);

    // warp w handles i_loc in {4w..4w+3}; all 64 j (4 m-tiles of 16); 4 n-tiles (32 o)
    for (int ii = 0; ii < 4; ii++) {
        const int iloc = w*4 + ii;
        const float* rcvp = &rcv_s[iloc*RCV_STR];

        float s[4][2];
        #pragma unroll
        for (int nt = 0; nt < 4; nt++) { s[nt][0] = 0.f; s[nt][1] = 0.f; }

        for (int mj = 0; mj < 4; mj++) {
            const float* sp = &snd_s[(mj*16 + rr)*SND_STR];
            float acc[4][4];
            #pragma unroll
            for (int nt = 0; nt < 4; nt++)
                { acc[nt][0]=0.f; acc[nt][1]=0.f; acc[nt][2]=0.f; acc[nt][3]=0.f; }

            #pragma unroll
            for (int ks = 0; ks < 8; ks++) {
                const int kb = ks*16 + 2*q;
                float2 rc0 = *(const float2*)&rcvp[kb];
                float2 rc1 = *(const float2*)&rcvp[kb + 8];
                float2 s00 = *(const float2*)&sp[kb];
                float2 s10 = *(const float2*)&sp[8*SND_STR + kb];
                float2 s01 = *(const float2*)&sp[kb + 8];
                float2 s11 = *(const float2*)&sp[8*SND_STR + kb + 8];

                __half2 a0 = __floats2half2_rn(s00.x + rc0.x, s00.y + rc0.y);
                __half2 a1 = __floats2half2_rn(s10.x + rc0.x, s10.y + rc0.y);
                __half2 a2 = __floats2half2_rn(s01.x + rc1.x, s01.y + rc1.y);
                __half2 a3 = __floats2half2_rn(s11.x + rc1.x, s11.y + rc1.y);
                a0 = __hmax2(a0, __hmul2(a0, alpha2));
                a1 = __hmax2(a1, __hmul2(a1, alpha2));
                a2 = __hmax2(a2, __hmul2(a2, alpha2));
                a3 = __hmax2(a3, __hmul2(a3, alpha2));
                const uint32_t A0 = *(uint32_t*)&a0, A1 = *(uint32_t*)&a1;
                const uint32_t A2 = *(uint32_t*)&a2, A3 = *(uint32_t*)&a3;

                #pragma unroll
                for (int nt = 0; nt < 4; nt++) {
                    const uint4 bb = breg[ks*2 + (nt >> 1)];
                    const uint32_t b0 = (nt & 1) ? bb.z : bb.x;
                    const uint32_t b1 = (nt & 1) ? bb.w : bb.y;
                    asm volatile("mma.sync.aligned.m16n8k16.row.col.f32.f16.f16.f32 "
                                 "{%0,%1,%2,%3}, {%4,%5,%6,%7}, {%8,%9}, {%0,%1,%2,%3};"
                                 : "+f"(acc[nt][0]), "+f"(acc[nt][1]),
                                   "+f"(acc[nt][2]), "+f"(acc[nt][3])
                                 : "r"(A0), "r"(A1), "r"(A2), "r"(A3), "r"(b0), "r"(b1));
                }
            }

            // drain: lrelu(acc + be2), sum over the 16 j-rows of this m-tile
            #pragma unroll
            for (int nt = 0; nt < 4; nt++) {
                const float o0 = be2s[nt*8 + 2*q], o1 = be2s[nt*8 + 2*q + 1];
                s[nt][0] += lrelu(acc[nt][0] + o0) + lrelu(acc[nt][2] + o0);
                s[nt][1] += lrelu(acc[nt][1] + o1) + lrelu(acc[nt][3] + o1);
            }
        }

        // reduce j-sums across rr groups (lanes sharing q)
        #pragma unroll
        for (int nt = 0; nt < 4; nt++) {
            #pragma unroll
            for (int e = 0; e < 2; e++) {
                float v = s[nt][e];
                v += __shfl_xor_sync(0xFFFFFFFFu, v, 4);
                v += __shfl_xor_sync(0xFFFFFFFFu, v, 8);
                v += __shfl_xor_sync(0xFFFFFFFFu, v, 16);
                s[nt][e] = v;
            }
        }
        if (lane < 4) {    // lane == q, rr == 0
            const int row = b*Nn + it*32 + iloc;
            float* dst = &g_mp[jt][row][oh*32];
            #pragma unroll
            for (int nt = 0; nt < 4; nt++)
                *(float2*)&dst[nt*8 + 2*q] = make_float2(s[nt][0], s[nt][1]);
        }
    }
}

// ---------------- K4: node update (sums the 4 j-tile partials) ----------------
__global__ void k_node(const float* __restrict__ Wn0_t, const float* __restrict__ bn0_t,
                       const float* __restrict__ Wn1_t, const float* __restrict__ bn1_t,
                       float* __restrict__ out, int last) {
    const int row = blockIdx.x, o = threadIdx.x;
    __shared__ float fs[Hh + EOo];
    __shared__ float n0s[Hh];
    fs[o] = g_h[(size_t)row*Hh + o];
    {
        float m0 = 0.f, m1 = 0.f;
        #pragma unroll
        for (int jtt = 0; jtt < 4; jtt++) {
            m0 += g_mp[jtt][row][o];
            m1 += g_mp[jtt][row][Hh + o];
        }
        fs[Hh + o]      = m0;
        fs[Hh + Hh + o] = m1;
    }
    __syncthreads();
    float a = bn0_t[o];
    #pragma unroll
    for (int f = 0; f < Hh + EOo; f++) a += fs[f] * Wn0_t[f*Hh + o];
    n0s[o] = lrelu(a);
    __syncthreads();
    float a2 = bn1_t[o];
    #pragma unroll
    for (int f = 0; f < Hh; f++) a2 += n0s[f] * Wn1_t[f*Hh + o];
    a2 = lrelu(a2);
    if (last) out[(size_t)row*Hh + o] = tanhf(a2);
    else      g_h[(size_t)row*Hh + o] = a2;
}

// ---------------- launch ----------------
extern "C" void kernel_launch(void* const* d_in, const int* in_sizes, int n_in,
                              void* d_out, int out_size) {
    const float* x     = (const float*)d_in[0];
    const float* W_lin = (const float*)d_in[1];
    const float* b_lin = (const float*)d_in[2];
    const float* W_in  = (const float*)d_in[3];
    const float* b_in  = (const float*)d_in[4];
    const float* We1   = (const float*)d_in[5];
    const float* be1   = (const float*)d_in[6];
    const float* We2   = (const float*)d_in[7];
    const float* be2   = (const float*)d_in[8];
    const float* Wn0   = (const float*)d_in[9];
    const float* bn0   = (const float*)d_in[10];
    const float* Wn1   = (const float*)d_in[11];
    const float* bn1   = (const float*)d_in[12];
    float* out = (float*)d_out;

    cudaFuncSetAttribute(k_edge4, cudaFuncAttributeMaxDynamicSharedMemorySize, EDGE_SMEM);

    k_init<<<Bsz*Nn, 64>>>(x, W_lin, b_lin, W_in, b_in);
    for (int t = 0; t < 3; t++) {
        k_prep<<<1, 256>>>(We2 + (size_t)t * HEe*EOo);
        k_rs  <<<(Bsz*Nn)/32, 128>>>(We1 + (size_t)t * 2*Hh*HEe);
        k_edge4<<<Bsz*8*4*2, 256, EDGE_SMEM>>>(be1 + t*HEe, be2 + t*EOo);
        k_node<<<Bsz*Nn, 32>>>(Wn0 + (size_t)t * (Hh+EOo)*Hh, bn0 + t*Hh,
                               Wn1 + (size_t)t * Hh*Hh,        bn1 + t*Hh,
                               out, t == 2);
    }
}